// round 13
// baseline (speedup 1.0000x reference)
#include <cuda_runtime.h>
#include <math.h>

#define Bn 8
#define Nn 8192
#define Sn 2048
#define Dn 64
#define KS 32
#define MTOT (Bn*Sn*KS)            /* 524288 rows through the MLP */
#define R2c 0.25f
#define NWORK 140                  /* worker blocks in fused kernel */
#define WTILE 16                   /* centers per worker tile */
#define NTILES (Bn*Sn/WTILE)       /* 1024 */

#define OXY2 (Bn*3*Sn)             /* 49152  */
#define ONP  (2*Bn*3*Sn)           /* 98304  */
#define OFPS (ONP + Bn*128*Sn)     /* 2195456 */

/* ------------------------- static device scratch ------------------------- */
__device__ float  g_pts_t[(size_t)Bn*Nn*Dn];   /* [B][N][64] */
__device__ int    g_fps[Bn*Sn];
__device__ float  g_h0[(size_t)MTOT*64];
__device__ float  g_h1[(size_t)MTOT*64];
__device__ float  g_mx[(size_t)Bn*Sn*128];
__device__ float  g_mn[(size_t)Bn*Sn*128];
__device__ double g_sum[3][128];
__device__ double g_sq[3][128];
__device__ float  g_sc[3][128];
__device__ float  g_sh[3][128];
__device__ volatile int g_prog[Bn];

/* ------------------------- packed f32x2 helpers -------------------------- */
typedef unsigned long long ull;
__device__ __forceinline__ ull pk2(float lo, float hi) {
    ull r; asm("mov.b64 %0,{%1,%2};" : "=l"(r) : "f"(lo), "f"(hi)); return r;
}
__device__ __forceinline__ void upk2(ull v, float& lo, float& hi) {
    asm("mov.b64 {%0,%1},%2;" : "=f"(lo), "=f"(hi) : "l"(v));
}
__device__ __forceinline__ ull add2(ull a, ull b) {
    ull r; asm("add.rn.f32x2 %0,%1,%2;" : "=l"(r) : "l"(a), "l"(b)); return r;
}
__device__ __forceinline__ ull mul2(ull a, ull b) {
    ull r; asm("mul.rn.f32x2 %0,%1,%2;" : "=l"(r) : "l"(a), "l"(b)); return r;
}

/* --------------------- pre: transpose + zero + prog reset ---------------- */
__global__ void k_pre(const float* __restrict__ pts) {
    __shared__ float tile[32][33];
    int b = blockIdx.z, n0 = blockIdx.x * 32, c0 = blockIdx.y * 32;
    int tx = threadIdx.x, ty = threadIdx.y;
    if (blockIdx.x == 0 && blockIdx.y == 0 && blockIdx.z == 0) {
        int tid = ty*32 + tx;
        if (tid < 128) for (int l = 0; l < 3; l++) { g_sum[l][tid]=0.0; g_sq[l][tid]=0.0; }
        if (tid < Bn) g_prog[tid] = -1;
    }
    for (int i = ty; i < 32; i += 8)
        tile[i][tx] = pts[((size_t)b*Dn + c0 + i)*Nn + n0 + tx];
    __syncthreads();
    for (int i = ty; i < 32; i += 8)
        g_pts_t[((size_t)b*Nn + n0 + i)*Dn + c0 + tx] = tile[tx][i];
}

#define FMA4(A, H, WV) { (A)[0] += (H)*(WV).x; (A)[1] += (H)*(WV).y; \
                         (A)[2] += (H)*(WV).z; (A)[3] += (H)*(WV).w; }

/* floats of dynamic smem for the fused kernel (worker layout is the max) */
#define FS_HS   0                       /* 512*72 = 36864 */
#define FS_WSG  (512*72)                /* 72*64  = 4608  */
#define FS_WSB  (FS_WSG + 72*64)        /* 67*64  = 4288  */
#define FS_BS   (FS_WSB + 67*64)        /* 16*64  = 1024  */
#define FS_CF   (FS_BS + 1024)          /* 16*64  = 1024  */
#define FS_CXY  (FS_CF + 1024)          /* 48 */
#define FS_IDX  (FS_CXY + 48)           /* 512 ints */
#define FS_SSUM (FS_IDX + 512)          /* 64 */
#define FS_SSQ  (FS_SSUM + 64)          /* 64 */
#define FS_TOTAL (FS_SSQ + 64)          /* 48496 floats = 193984 B */

/* ------------------------------ FUSED ------------------------------------ */
/* blocks 0..7: FPS (one per batch), publishing progress every 8 iters.
   blocks 8..147: persistent workers — per 16-center tile: wait on progress,
   write xyz/fps outputs, ball-query (warps 0-15) || base staging (16-31),
   gather, 512x64x72 GEMM (layer 0) with W0 resident per block. */
__global__ void __launch_bounds__(1024) k_fused(const float* __restrict__ xyz,
                                                const float* __restrict__ W0,
                                                float* __restrict__ out) {
    extern __shared__ float sm[];
    __shared__ unsigned s_dv[2][32];
    __shared__ unsigned s_di[2][32];
    int t = threadIdx.x, warp = t >> 5, lane = t & 31;

    if (blockIdx.x < Bn) {
        /* --------------------------- FPS ---------------------------- */
        int b = blockIdx.x;
        float* sx = sm; float* sy = sm + Nn; float* sz = sm + 2*Nn;
        const float* xb = xyz + (size_t)b*3*Nn;
        for (int i = t; i < Nn; i += 1024) { sx[i]=xb[i]; sy[i]=xb[Nn+i]; sz[i]=xb[2*Nn+i]; }
        __syncthreads();
        ull px2[4], py2[4], pz2[4];
        float dist[8];
#pragma unroll
        for (int j = 0; j < 4; j++) {
            int i = t*8 + 2*j;
            px2[j] = pk2(sx[i], sx[i+1]);
            py2[j] = pk2(sy[i], sy[i+1]);
            pz2[j] = pk2(sz[i], sz[i+1]);
            dist[2*j] = 1e10f; dist[2*j+1] = 1e10f;
        }
        float fx = sx[0], fy = sy[0], fz = sz[0];
        if (t == 0) g_fps[b*Sn] = 0;
        for (int it = 1; it < Sn; it++) {
            ull nx = pk2(-fx, -fx), ny = pk2(-fy, -fy), nz = pk2(-fz, -fz);
            float bv = -1.0f; int bi = 0;
#pragma unroll
            for (int j = 0; j < 4; j++) {
                ull dx = add2(px2[j], nx);
                ull dy = add2(py2[j], ny);
                ull dz = add2(pz2[j], nz);
                ull s  = add2(add2(mul2(dx,dx), mul2(dy,dy)), mul2(dz,dz));
                float dlo, dhi; upk2(s, dlo, dhi);
                float n0 = fminf(dist[2*j],   dlo); dist[2*j]   = n0;
                if (n0 > bv) { bv = n0; bi = t*8 + 2*j; }
                float n1 = fminf(dist[2*j+1], dhi); dist[2*j+1] = n1;
                if (n1 > bv) { bv = n1; bi = t*8 + 2*j + 1; }
            }
            unsigned dvb  = __float_as_uint(bv);
            unsigned wmax = __reduce_max_sync(0xffffffffu, dvb);
            unsigned cand = (dvb == wmax) ? (unsigned)bi : 0xffffffffu;
            unsigned wbi  = __reduce_min_sync(0xffffffffu, cand);
            int p = it & 1;
            if (lane == 0) { s_dv[p][warp] = wmax; s_di[p][warp] = wbi; }
            __syncthreads();
            unsigned v    = s_dv[p][lane];
            unsigned gmax = __reduce_max_sync(0xffffffffu, v);
            unsigned c2   = (v == gmax) ? s_di[p][lane] : 0xffffffffu;
            unsigned gbi  = __reduce_min_sync(0xffffffffu, c2);
            fx = sx[gbi]; fy = sy[gbi]; fz = sz[gbi];
            if (t == 0) {
                g_fps[b*Sn + it] = (int)gbi;
                if ((it & 7) == 7) { __threadfence(); g_prog[b] = it; }
            }
        }
    } else {
        /* -------------------------- worker --------------------------- */
        int widx = blockIdx.x - Bn;
        float* hs  = sm + FS_HS;
        float* wsg = sm + FS_WSG;
        float* wsb = sm + FS_WSB;
        float* bs  = sm + FS_BS;
        float* cf  = sm + FS_CF;
        float* cxy = sm + FS_CXY;
        int*   idxs = (int*)(sm + FS_IDX);
        float* ssum = sm + FS_SSUM;
        float* ssq  = sm + FS_SSQ;
        for (int i = t; i < 72*64; i += 1024) {
            int cc = i >> 6, o = i & 63;
            float v = 0.f;
            if (cc < 64)      v = W0[(size_t)o*131 + 3 + cc];
            else if (cc < 67) v = W0[(size_t)o*131 + (cc - 64)];
            wsg[cc*64 + o] = v;
        }
        for (int i = t; i < 67*64; i += 1024) {
            int cc = i >> 6, o = i & 63;
            wsb[cc*64 + o] = (cc < 3) ? W0[(size_t)o*131 + cc]
                                      : W0[(size_t)o*131 + 67 + (cc - 3)];
        }
        if (t < 64) { ssum[t] = 0.f; ssq[t] = 0.f; }
        int rg = t >> 4, og = t & 15;
        float tps[4] = {0,0,0,0}, tpq[4] = {0,0,0,0};

        for (int tt = widx; tt < NTILES; tt += NWORK) {
            int b = tt >> 7, lt = tt & 127;
            const float* xb = xyz + (size_t)b*3*Nn;
            int cbase = b*Sn + lt*WTILE;
            int need = lt*WTILE + WTILE - 1;
            while (g_prog[b] < need) __nanosleep(256);
            __threadfence();
            __syncthreads();
            if (t < WTILE) {
                int s = lt*WTILE + t;
                int n = g_fps[b*Sn + s];
                float x = xb[n], y = xb[Nn+n], z = xb[2*Nn+n];
                out[((size_t)b*3+0)*Sn + s] = x;
                out[((size_t)b*3+1)*Sn + s] = y;
                out[((size_t)b*3+2)*Sn + s] = z;
                out[OXY2 + ((size_t)b*3+0)*Sn + s] = x;
                out[OXY2 + ((size_t)b*3+1)*Sn + s] = y;
                out[OXY2 + ((size_t)b*3+2)*Sn + s] = z;
                out[OFPS + b*Sn + s] = (float)n;
            }
            if (warp < 16) {
                /* ball query, warp per center, first-32-in-order */
                int s = lt*WTILE + warp;
                int n = g_fps[b*Sn + s];
                float cx = xb[n], cy = xb[Nn+n], cz = xb[2*Nn+n];
                int found = 0, first = -1;
                for (int nb = 0; nb < Nn && found < KS; nb += 32) {
                    int i = nb + lane;
                    float dx = __fadd_rn(cx, -xb[i]);
                    float dy = __fadd_rn(cy, -xb[Nn+i]);
                    float dz = __fadd_rn(cz, -xb[2*Nn+i]);
                    float d2 = __fadd_rn(__fadd_rn(__fmul_rn(dx,dx), __fmul_rn(dy,dy)),
                                         __fmul_rn(dz,dz));
                    unsigned m = __ballot_sync(0xffffffffu, d2 <= R2c);
                    if (m) {
                        if (first < 0) first = nb + __ffs(m) - 1;
                        int pos = found + __popc(m & ((1u << lane) - 1u));
                        if (((m >> lane) & 1u) && pos < KS) idxs[warp*KS + pos] = i;
                        found += __popc(m);
                    }
                }
                if (found < KS && lane >= found && lane < KS) idxs[warp*KS + lane] = first;
            } else {
                int ti = t - 512;
                if (ti < 256) {
                    int row = ti >> 4, seg = ti & 15;
                    int n = g_fps[b*Sn + lt*WTILE + row];
                    *(float4*)&cf[row*64 + seg*4] =
                        *(const float4*)&g_pts_t[((size_t)b*Nn + n)*Dn + seg*4];
                } else if (ti < 304) {
                    int k = ti - 256;        /* 0..47 */
                    int cl = k / 3, d = k % 3;
                    int n = g_fps[b*Sn + lt*WTILE + cl];
                    cxy[k] = xb[d*Nn + n];
                }
            }
            __syncthreads();
            /* gather hs rows */
            for (int i = t; i < 512*16; i += 1024) {
                int row = i >> 4, seg = i & 15;
                int n = idxs[row];
                *(float4*)&hs[row*72 + seg*4] =
                    *(const float4*)&g_pts_t[((size_t)b*Nn + n)*Dn + seg*4];
            }
            for (int i = t; i < 512*8; i += 1024) {
                int row = i >> 3, cc = i & 7;
                float v = 0.f;
                if (cc < 3) v = xb[cc*Nn + idxs[row]];
                hs[row*72 + 64 + cc] = v;
            }
            /* base GEMV: threads 512..1023 */
            if (t >= 512) {
                int ti = t - 512;
#pragma unroll
                for (int pp = 0; pp < 2; pp++) {
                    int p = ti + pp*512;
                    int cl = p >> 6, o = p & 63;
                    float acc = -(cxy[cl*3+0]*wsb[o] + cxy[cl*3+1]*wsb[64+o]
                                 + cxy[cl*3+2]*wsb[128+o]);
#pragma unroll 8
                    for (int k = 0; k < 64; k++) acc += cf[cl*64 + k]*wsb[(3+k)*64 + o];
                    bs[cl*64 + o] = acc;
                }
            }
            __syncthreads();
            /* layer-0 GEMM: 512 rows x 64 outs, 8x4 per thread */
            float acc[32];
#pragma unroll
            for (int i = 0; i < 32; i++) acc[i] = 0.f;
#pragma unroll
            for (int cs = 0; cs < 72; cs += 4) {
                float4 wv[4];
#pragma unroll
                for (int i = 0; i < 4; i++) wv[i] = *(const float4*)&wsg[(cs+i)*64 + og*4];
#pragma unroll
                for (int j = 0; j < 8; j++) {
                    float4 hv = *(const float4*)&hs[(rg*8+j)*72 + cs];
                    FMA4(&acc[j*4], hv.x, wv[0]);
                    FMA4(&acc[j*4], hv.y, wv[1]);
                    FMA4(&acc[j*4], hv.z, wv[2]);
                    FMA4(&acc[j*4], hv.w, wv[3]);
                }
            }
            size_t m0 = (size_t)cbase * KS;
#pragma unroll
            for (int j = 0; j < 8; j++) {
                int row = rg*8 + j;
                int cl = row >> 5;
                float4 zv;
                zv.x = acc[j*4+0] + bs[cl*64 + og*4+0];
                zv.y = acc[j*4+1] + bs[cl*64 + og*4+1];
                zv.z = acc[j*4+2] + bs[cl*64 + og*4+2];
                zv.w = acc[j*4+3] + bs[cl*64 + og*4+3];
                *(float4*)&g_h0[(m0 + row)*64 + og*4] = zv;
                tps[0]+=zv.x; tps[1]+=zv.y; tps[2]+=zv.z; tps[3]+=zv.w;
                tpq[0]+=zv.x*zv.x; tpq[1]+=zv.y*zv.y; tpq[2]+=zv.z*zv.z; tpq[3]+=zv.w*zv.w;
            }
        }
        __syncthreads();
#pragma unroll
        for (int i = 0; i < 4; i++) {
            atomicAdd(&ssum[og*4+i], tps[i]);
            atomicAdd(&ssq[og*4+i],  tpq[i]);
        }
        __syncthreads();
        if (t < 64) {
            atomicAdd(&g_sum[0][t], (double)ssum[t]);
            atomicAdd(&g_sq[0][t],  (double)ssq[t]);
        }
    }
}

/* ------------------------------ layer 1 ---------------------------------- */
__global__ void __launch_bounds__(128) k_layer1(const float* __restrict__ W1) {
    __shared__ float hs[128*64];
    __shared__ float ws[64*64];
    __shared__ float ssum[64], ssq[64];
    int t = threadIdx.x;
    if (t < 64) { ssum[t] = 0.f; ssq[t] = 0.f; }
    for (int i = t; i < 64*64; i += 128) {
        int cc = i >> 6, o = i & 63;
        ws[cc*64 + o] = W1[(size_t)o*64 + cc];
    }
    int rg = t >> 3, og = (t & 7) * 8;
    for (int tile = 0; tile < 2; tile++) {
        size_t m0 = (size_t)blockIdx.x * 256 + tile * 128;
        __syncthreads();
        for (int i = t; i < 128*16; i += 128) {
            int row = i >> 4, seg = i & 15;
            float4 v = *(const float4*)&g_h0[(m0 + row)*64 + seg*4];
            v.x = fmaxf(g_sc[0][seg*4+0]*v.x + g_sh[0][seg*4+0], 0.f);
            v.y = fmaxf(g_sc[0][seg*4+1]*v.y + g_sh[0][seg*4+1], 0.f);
            v.z = fmaxf(g_sc[0][seg*4+2]*v.z + g_sh[0][seg*4+2], 0.f);
            v.w = fmaxf(g_sc[0][seg*4+3]*v.w + g_sh[0][seg*4+3], 0.f);
            *(float4*)&hs[row*64 + seg*4] = v;
        }
        __syncthreads();
        float acc[64];
#pragma unroll
        for (int i = 0; i < 64; i++) acc[i] = 0.f;
#pragma unroll
        for (int cs = 0; cs < 64; cs += 4) {
            float4 wv[8];
#pragma unroll
            for (int c = 0; c < 4; c++) {
                wv[c*2]   = *(const float4*)&ws[(cs+c)*64 + og];
                wv[c*2+1] = *(const float4*)&ws[(cs+c)*64 + og + 4];
            }
#pragma unroll
            for (int j = 0; j < 8; j++) {
                float4 hv = *(const float4*)&hs[(rg*8+j)*64 + cs];
                float* a = &acc[j*8];
                FMA4(a,   hv.x, wv[0]); FMA4(a+4, hv.x, wv[1]);
                FMA4(a,   hv.y, wv[2]); FMA4(a+4, hv.y, wv[3]);
                FMA4(a,   hv.z, wv[4]); FMA4(a+4, hv.z, wv[5]);
                FMA4(a,   hv.w, wv[6]); FMA4(a+4, hv.w, wv[7]);
            }
        }
        float ps[8] = {0,0,0,0,0,0,0,0}, pq[8] = {0,0,0,0,0,0,0,0};
#pragma unroll
        for (int j = 0; j < 8; j++) {
            int row = rg*8 + j;
            float4 z0 = make_float4(acc[j*8+0], acc[j*8+1], acc[j*8+2], acc[j*8+3]);
            float4 z1 = make_float4(acc[j*8+4], acc[j*8+5], acc[j*8+6], acc[j*8+7]);
            *(float4*)&g_h1[(m0 + row)*64 + og]     = z0;
            *(float4*)&g_h1[(m0 + row)*64 + og + 4] = z1;
#pragma unroll
            for (int k = 0; k < 8; k++) {
                float z = acc[j*8+k];
                ps[k] += z; pq[k] += z*z;
            }
        }
#pragma unroll
        for (int k = 0; k < 8; k++) {
            atomicAdd(&ssum[og+k], ps[k]);
            atomicAdd(&ssq[og+k],  pq[k]);
        }
    }
    __syncthreads();
    if (t < 64) {
        atomicAdd(&g_sum[1][t], (double)ssum[t]);
        atomicAdd(&g_sq[1][t],  (double)ssq[t]);
    }
}

/* ------------------------------ layer 2 ---------------------------------- */
__global__ void __launch_bounds__(128) k_layer2(const float* __restrict__ W2) {
    extern __shared__ float dyn[];
    float* hs    = dyn;                  /* 64*64  = 4096  */
    float* ws    = dyn + 4096;           /* 64*128 = 8192  */
    float* redmx = dyn + 4096 + 8192;    /* 8*128  = 1024  */
    float* redmn = redmx + 1024;         /* 1024  */
    float* ssum  = redmn + 1024;         /* 128   */
    float* ssq   = ssum + 128;           /* 128   */
    int t = threadIdx.x;
    if (t < 128) { ssum[t] = 0.f; ssq[t] = 0.f; }
    for (int i = t; i < 64*128; i += 128) {
        int cc = i >> 7, o = i & 127;
        ws[cc*128 + o] = W2[(size_t)o*64 + cc];
    }
    int rg = t >> 4, og = (t & 15) * 8;
    for (int tile = 0; tile < 2; tile++) {
        int c0 = blockIdx.x * 4 + tile * 2;
        size_t m0 = (size_t)c0 * KS;
        __syncthreads();
        for (int i = t; i < 64*16; i += 128) {
            int row = i >> 4, seg = i & 15;
            float4 v = *(const float4*)&g_h1[(m0 + row)*64 + seg*4];
            v.x = fmaxf(g_sc[1][seg*4+0]*v.x + g_sh[1][seg*4+0], 0.f);
            v.y = fmaxf(g_sc[1][seg*4+1]*v.y + g_sh[1][seg*4+1], 0.f);
            v.z = fmaxf(g_sc[1][seg*4+2]*v.z + g_sh[1][seg*4+2], 0.f);
            v.w = fmaxf(g_sc[1][seg*4+3]*v.w + g_sh[1][seg*4+3], 0.f);
            *(float4*)&hs[row*64 + seg*4] = v;
        }
        __syncthreads();
        float acc[64];
#pragma unroll
        for (int i = 0; i < 64; i++) acc[i] = 0.f;
#pragma unroll
        for (int cs = 0; cs < 64; cs += 4) {
            float4 wv[8];
#pragma unroll
            for (int c = 0; c < 4; c++) {
                wv[c*2]   = *(const float4*)&ws[(cs+c)*128 + og];
                wv[c*2+1] = *(const float4*)&ws[(cs+c)*128 + og + 4];
            }
#pragma unroll
            for (int j = 0; j < 8; j++) {
                float4 hv = *(const float4*)&hs[(rg*8+j)*64 + cs];
                float* a = &acc[j*8];
                FMA4(a,   hv.x, wv[0]); FMA4(a+4, hv.x, wv[1]);
                FMA4(a,   hv.y, wv[2]); FMA4(a+4, hv.y, wv[3]);
                FMA4(a,   hv.z, wv[4]); FMA4(a+4, hv.z, wv[5]);
                FMA4(a,   hv.w, wv[6]); FMA4(a+4, hv.w, wv[7]);
            }
        }
#pragma unroll
        for (int k = 0; k < 8; k++) {
            int o = og + k;
            float mx = -1e30f, mn = 1e30f, ps = 0.f, pq = 0.f;
#pragma unroll
            for (int j = 0; j < 8; j++) {
                float z = acc[j*8+k];
                mx = fmaxf(mx, z); mn = fminf(mn, z);
                ps += z; pq += z*z;
            }
            redmx[rg*128 + o] = mx;
            redmn[rg*128 + o] = mn;
            atomicAdd(&ssum[o], ps);
            atomicAdd(&ssq[o],  pq);
        }
        __syncthreads();
#pragma unroll
        for (int p = t; p < 256; p += 128) {
            int cl = p >> 7, o = p & 127;
            float mx = -1e30f, mn = 1e30f;
#pragma unroll
            for (int r = 0; r < 4; r++) {
                mx = fmaxf(mx, redmx[(cl*4+r)*128 + o]);
                mn = fminf(mn, redmn[(cl*4+r)*128 + o]);
            }
            g_mx[(size_t)(c0+cl)*128 + o] = mx;
            g_mn[(size_t)(c0+cl)*128 + o] = mn;
        }
    }
    __syncthreads();
    if (t < 128) {
        atomicAdd(&g_sum[2][t], (double)ssum[t]);
        atomicAdd(&g_sq[2][t],  (double)ssq[t]);
    }
}

/* ----------------------------- BN fold ----------------------------------- */
__global__ void k_stats(int layer, const float* __restrict__ gm,
                        const float* __restrict__ bt, int nch) {
    int c = threadIdx.x;
    if (c < nch) {
        double mu = g_sum[layer][c] / (double)MTOT;
        double vr = g_sq[layer][c] / (double)MTOT - mu*mu;
        float sc = gm[c] * rsqrtf((float)vr + 1e-5f);
        g_sc[layer][c] = sc;
        g_sh[layer][c] = bt[c] - (float)mu * sc;
    }
}

/* ----------------------------- final pool -------------------------------- */
__global__ void k_final(float* __restrict__ out) {
    int i = blockIdx.x * blockDim.x + threadIdx.x;
    if (i >= Bn*Sn*128) return;
    int center = i >> 7, o = i & 127;
    int b = center / Sn, s = center % Sn;
    float sc = g_sc[2][o], sh = g_sh[2][o];
    float z = (sc >= 0.f) ? g_mx[(size_t)center*128 + o] : g_mn[(size_t)center*128 + o];
    out[ONP + ((size_t)b*128 + o)*Sn + s] = fmaxf(sc*z + sh, 0.f);
}

/* ------------------------------- launch ---------------------------------- */
extern "C" void kernel_launch(void* const* d_in, const int* in_sizes, int n_in,
                              void* d_out, int out_size) {
    const float* xyz = (const float*)d_in[0];
    const float* pts = (const float*)d_in[1];
    const float* W0  = (const float*)d_in[2];
    const float* g0  = (const float*)d_in[3];
    const float* b0  = (const float*)d_in[4];
    const float* W1  = (const float*)d_in[5];
    const float* g1  = (const float*)d_in[6];
    const float* b1  = (const float*)d_in[7];
    const float* W2  = (const float*)d_in[8];
    const float* g2  = (const float*)d_in[9];
    const float* b2  = (const float*)d_in[10];
    float* out = (float*)d_out;

    static bool attr_done = false;
    if (!attr_done) {
        cudaFuncSetAttribute(k_fused, cudaFuncAttributeMaxDynamicSharedMemorySize,
                             FS_TOTAL*sizeof(float));
        cudaFuncSetAttribute(k_layer2, cudaFuncAttributeMaxDynamicSharedMemorySize,
                             (4096+8192+1024+1024+256)*sizeof(float));
        attr_done = true;
    }

    k_pre<<<dim3(Nn/32, Dn/32, Bn), dim3(32, 8)>>>(pts);
    k_fused<<<Bn + NWORK, 1024, FS_TOTAL*sizeof(float)>>>(xyz, W0, out);
    k_stats<<<1, 128>>>(0, g0, b0, 64);
    k_layer1<<<MTOT/256, 128>>>(W1);
    k_stats<<<1, 128>>>(1, g1, b1, 64);
    k_layer2<<<Bn*Sn/4, 128, (4096+8192+1024+1024+256)*sizeof(float)>>>(W2);
    k_stats<<<1, 128>>>(2, g2, b2, 128);
    k_final<<<(Bn*Sn*128 + 255)/256, 256>>>(out);
}

// round 16
// speedup vs baseline: 1.0287x; 1.0287x over previous
#include <cuda_runtime.h>
#include <math.h>

#define Bn 8
#define Nn 8192
#define Sn 2048
#define Dn 64
#define KS 32
#define MTOT (Bn*Sn*KS)            /* 524288 rows through the MLP */
#define R2c 0.25f
#define NWORK 140                  /* worker blocks in fused kernel */
#define WTILE 16                   /* centers per worker tile */
#define NTILES (Bn*Sn/WTILE)       /* 1024 */

#define OXY2 (Bn*3*Sn)             /* 49152  */
#define ONP  (2*Bn*3*Sn)           /* 98304  */
#define OFPS (ONP + Bn*128*Sn)     /* 2195456 */

/* ------------------------- static device scratch ------------------------- */
__device__ float  g_pts_t[(size_t)Bn*Nn*Dn];   /* [B][N][64] */
__device__ int    g_fps[Bn*Sn];
__device__ float  g_h0[(size_t)MTOT*64];
__device__ float  g_h1[(size_t)MTOT*64];
__device__ float  g_mx[(size_t)Bn*Sn*128];
__device__ float  g_mn[(size_t)Bn*Sn*128];
__device__ double g_sum[3][128];
__device__ double g_sq[3][128];
__device__ float  g_sc[3][128];
__device__ float  g_sh[3][128];
__device__ volatile int g_prog[Bn];

/* ------------------------- packed f32x2 helpers -------------------------- */
typedef unsigned long long ull;
__device__ __forceinline__ ull pk2(float lo, float hi) {
    ull r; asm("mov.b64 %0,{%1,%2};" : "=l"(r) : "f"(lo), "f"(hi)); return r;
}
__device__ __forceinline__ void upk2(ull v, float& lo, float& hi) {
    asm("mov.b64 {%0,%1},%2;" : "=f"(lo), "=f"(hi) : "l"(v));
}
__device__ __forceinline__ ull add2(ull a, ull b) {
    ull r; asm("add.rn.f32x2 %0,%1,%2;" : "=l"(r) : "l"(a), "l"(b)); return r;
}
__device__ __forceinline__ ull mul2(ull a, ull b) {
    ull r; asm("mul.rn.f32x2 %0,%1,%2;" : "=l"(r) : "l"(a), "l"(b)); return r;
}

/* --------------------- pre: transpose + zero + prog reset ---------------- */
__global__ void k_pre(const float* __restrict__ pts) {
    __shared__ float tile[32][33];
    int b = blockIdx.z, n0 = blockIdx.x * 32, c0 = blockIdx.y * 32;
    int tx = threadIdx.x, ty = threadIdx.y;
    if (blockIdx.x == 0 && blockIdx.y == 0 && blockIdx.z == 0) {
        int tid = ty*32 + tx;
        if (tid < 128) for (int l = 0; l < 3; l++) { g_sum[l][tid]=0.0; g_sq[l][tid]=0.0; }
        if (tid < Bn) g_prog[tid] = -1;
    }
    for (int i = ty; i < 32; i += 8)
        tile[i][tx] = pts[((size_t)b*Dn + c0 + i)*Nn + n0 + tx];
    __syncthreads();
    for (int i = ty; i < 32; i += 8)
        g_pts_t[((size_t)b*Nn + n0 + i)*Dn + c0 + tx] = tile[tx][i];
}

#define FMA4(A, H, WV) { (A)[0] += (H)*(WV).x; (A)[1] += (H)*(WV).y; \
                         (A)[2] += (H)*(WV).z; (A)[3] += (H)*(WV).w; }

/* floats of dynamic smem for the fused kernel (worker layout is the max) */
#define FS_HS   0                       /* 512*72 = 36864 */
#define FS_WSG  (512*72)                /* 72*64  = 4608  */
#define FS_WSB  (FS_WSG + 72*64)        /* 67*64  = 4288  */
#define FS_BS   (FS_WSB + 67*64)        /* 16*64  = 1024  */
#define FS_CF   (FS_BS + 1024)          /* 16*64  = 1024  */
#define FS_CXY  (FS_CF + 1024)          /* 48 */
#define FS_IDX  (FS_CXY + 48)           /* 512 ints */
#define FS_SSUM (FS_IDX + 512)          /* 64 */
#define FS_SSQ  (FS_SSUM + 64)          /* 64 */
#define FS_TOTAL (FS_SSQ + 64)          /* 48496 floats = 193984 B */

/* ------------------------------ FUSED ------------------------------------ */
/* blocks 0..7: FPS (one per batch), publishing progress every 8 iters.
   blocks 8..147: persistent workers. ONLY thread 0 of a worker block polls
   the progress flag (poll storm from 140k threads was throttling the FPS
   producer's L2 partition); __syncthreads releases the block; g_fps reads
   use __ldcg (L2) to avoid stale L1. */
__global__ void __launch_bounds__(1024) k_fused(const float* __restrict__ xyz,
                                                const float* __restrict__ W0,
                                                float* __restrict__ out) {
    extern __shared__ float sm[];
    __shared__ unsigned s_dv[2][32];
    __shared__ unsigned s_di[2][32];
    int t = threadIdx.x, warp = t >> 5, lane = t & 31;

    if (blockIdx.x < Bn) {
        /* --------------------------- FPS ---------------------------- */
        int b = blockIdx.x;
        float* sx = sm; float* sy = sm + Nn; float* sz = sm + 2*Nn;
        const float* xb = xyz + (size_t)b*3*Nn;
        for (int i = t; i < Nn; i += 1024) { sx[i]=xb[i]; sy[i]=xb[Nn+i]; sz[i]=xb[2*Nn+i]; }
        __syncthreads();
        ull px2[4], py2[4], pz2[4];
        float dist[8];
#pragma unroll
        for (int j = 0; j < 4; j++) {
            int i = t*8 + 2*j;
            px2[j] = pk2(sx[i], sx[i+1]);
            py2[j] = pk2(sy[i], sy[i+1]);
            pz2[j] = pk2(sz[i], sz[i+1]);
            dist[2*j] = 1e10f; dist[2*j+1] = 1e10f;
        }
        float fx = sx[0], fy = sy[0], fz = sz[0];
        if (t == 0) g_fps[b*Sn] = 0;
        for (int it = 1; it < Sn; it++) {
            ull nx = pk2(-fx, -fx), ny = pk2(-fy, -fy), nz = pk2(-fz, -fz);
            float bv = -1.0f; int bi = 0;
#pragma unroll
            for (int j = 0; j < 4; j++) {
                ull dx = add2(px2[j], nx);
                ull dy = add2(py2[j], ny);
                ull dz = add2(pz2[j], nz);
                ull s  = add2(add2(mul2(dx,dx), mul2(dy,dy)), mul2(dz,dz));
                float dlo, dhi; upk2(s, dlo, dhi);
                float n0 = fminf(dist[2*j],   dlo); dist[2*j]   = n0;
                if (n0 > bv) { bv = n0; bi = t*8 + 2*j; }
                float n1 = fminf(dist[2*j+1], dhi); dist[2*j+1] = n1;
                if (n1 > bv) { bv = n1; bi = t*8 + 2*j + 1; }
            }
            unsigned dvb  = __float_as_uint(bv);
            unsigned wmax = __reduce_max_sync(0xffffffffu, dvb);
            unsigned cand = (dvb == wmax) ? (unsigned)bi : 0xffffffffu;
            unsigned wbi  = __reduce_min_sync(0xffffffffu, cand);
            int p = it & 1;
            if (lane == 0) { s_dv[p][warp] = wmax; s_di[p][warp] = wbi; }
            __syncthreads();
            unsigned v    = s_dv[p][lane];
            unsigned gmax = __reduce_max_sync(0xffffffffu, v);
            unsigned c2   = (v == gmax) ? s_di[p][lane] : 0xffffffffu;
            unsigned gbi  = __reduce_min_sync(0xffffffffu, c2);
            fx = sx[gbi]; fy = sy[gbi]; fz = sz[gbi];
            if (t == 0) {
                g_fps[b*Sn + it] = (int)gbi;
                if ((it & 7) == 7) { __threadfence(); g_prog[b] = it; }
            }
        }
    } else {
        /* -------------------------- worker --------------------------- */
        int widx = blockIdx.x - Bn;
        float* hs  = sm + FS_HS;
        float* wsg = sm + FS_WSG;
        float* wsb = sm + FS_WSB;
        float* bs  = sm + FS_BS;
        float* cf  = sm + FS_CF;
        float* cxy = sm + FS_CXY;
        int*   idxs = (int*)(sm + FS_IDX);
        float* ssum = sm + FS_SSUM;
        float* ssq  = sm + FS_SSQ;
        for (int i = t; i < 72*64; i += 1024) {
            int cc = i >> 6, o = i & 63;
            float v = 0.f;
            if (cc < 64)      v = W0[(size_t)o*131 + 3 + cc];
            else if (cc < 67) v = W0[(size_t)o*131 + (cc - 64)];
            wsg[cc*64 + o] = v;
        }
        for (int i = t; i < 67*64; i += 1024) {
            int cc = i >> 6, o = i & 63;
            wsb[cc*64 + o] = (cc < 3) ? W0[(size_t)o*131 + cc]
                                      : W0[(size_t)o*131 + 67 + (cc - 3)];
        }
        if (t < 64) { ssum[t] = 0.f; ssq[t] = 0.f; }
        int rg = t >> 4, og = t & 15;
        float tps[4] = {0,0,0,0}, tpq[4] = {0,0,0,0};

        for (int tt = widx; tt < NTILES; tt += NWORK) {
            int b = tt >> 7, lt = tt & 127;
            const float* xb = xyz + (size_t)b*3*Nn;
            int cbase = b*Sn + lt*WTILE;
            int need = lt*WTILE + WTILE - 1;
            if (t == 0) {                       /* single-thread poll */
                while (g_prog[b] < need) __nanosleep(1024);
            }
            __syncthreads();
            if (t < WTILE) {
                int s = lt*WTILE + t;
                int n = __ldcg(&g_fps[b*Sn + s]);
                float x = xb[n], y = xb[Nn+n], z = xb[2*Nn+n];
                out[((size_t)b*3+0)*Sn + s] = x;
                out[((size_t)b*3+1)*Sn + s] = y;
                out[((size_t)b*3+2)*Sn + s] = z;
                out[OXY2 + ((size_t)b*3+0)*Sn + s] = x;
                out[OXY2 + ((size_t)b*3+1)*Sn + s] = y;
                out[OXY2 + ((size_t)b*3+2)*Sn + s] = z;
                out[OFPS + b*Sn + s] = (float)n;
            }
            if (warp < 16) {
                /* ball query, warp per center, first-32-in-order */
                int s = lt*WTILE + warp;
                int n = __ldcg(&g_fps[b*Sn + s]);
                float cx = xb[n], cy = xb[Nn+n], cz = xb[2*Nn+n];
                int found = 0, first = -1;
                for (int nb = 0; nb < Nn && found < KS; nb += 32) {
                    int i = nb + lane;
                    float dx = __fadd_rn(cx, -xb[i]);
                    float dy = __fadd_rn(cy, -xb[Nn+i]);
                    float dz = __fadd_rn(cz, -xb[2*Nn+i]);
                    float d2 = __fadd_rn(__fadd_rn(__fmul_rn(dx,dx), __fmul_rn(dy,dy)),
                                         __fmul_rn(dz,dz));
                    unsigned m = __ballot_sync(0xffffffffu, d2 <= R2c);
                    if (m) {
                        if (first < 0) first = nb + __ffs(m) - 1;
                        int pos = found + __popc(m & ((1u << lane) - 1u));
                        if (((m >> lane) & 1u) && pos < KS) idxs[warp*KS + pos] = i;
                        found += __popc(m);
                    }
                }
                if (found < KS && lane >= found && lane < KS) idxs[warp*KS + lane] = first;
            } else {
                int ti = t - 512;
                if (ti < 256) {
                    int row = ti >> 4, seg = ti & 15;
                    int n = __ldcg(&g_fps[b*Sn + lt*WTILE + row]);
                    *(float4*)&cf[row*64 + seg*4] =
                        *(const float4*)&g_pts_t[((size_t)b*Nn + n)*Dn + seg*4];
                } else if (ti < 304) {
                    int k = ti - 256;        /* 0..47 */
                    int cl = k / 3, d = k % 3;
                    int n = __ldcg(&g_fps[b*Sn + lt*WTILE + cl]);
                    cxy[k] = xb[d*Nn + n];
                }
            }
            __syncthreads();
            /* gather hs rows */
            for (int i = t; i < 512*16; i += 1024) {
                int row = i >> 4, seg = i & 15;
                int n = idxs[row];
                *(float4*)&hs[row*72 + seg*4] =
                    *(const float4*)&g_pts_t[((size_t)b*Nn + n)*Dn + seg*4];
            }
            for (int i = t; i < 512*8; i += 1024) {
                int row = i >> 3, cc = i & 7;
                float v = 0.f;
                if (cc < 3) v = xb[cc*Nn + idxs[row]];
                hs[row*72 + 64 + cc] = v;
            }
            /* base GEMV: threads 512..1023 */
            if (t >= 512) {
                int ti = t - 512;
#pragma unroll
                for (int pp = 0; pp < 2; pp++) {
                    int p = ti + pp*512;
                    int cl = p >> 6, o = p & 63;
                    float acc = -(cxy[cl*3+0]*wsb[o] + cxy[cl*3+1]*wsb[64+o]
                                 + cxy[cl*3+2]*wsb[128+o]);
#pragma unroll 8
                    for (int k = 0; k < 64; k++) acc += cf[cl*64 + k]*wsb[(3+k)*64 + o];
                    bs[cl*64 + o] = acc;
                }
            }
            __syncthreads();
            /* layer-0 GEMM: 512 rows x 64 outs, 8x4 per thread */
            float acc[32];
#pragma unroll
            for (int i = 0; i < 32; i++) acc[i] = 0.f;
#pragma unroll
            for (int cs = 0; cs < 72; cs += 4) {
                float4 wv[4];
#pragma unroll
                for (int i = 0; i < 4; i++) wv[i] = *(const float4*)&wsg[(cs+i)*64 + og*4];
#pragma unroll
                for (int j = 0; j < 8; j++) {
                    float4 hv = *(const float4*)&hs[(rg*8+j)*72 + cs];
                    FMA4(&acc[j*4], hv.x, wv[0]);
                    FMA4(&acc[j*4], hv.y, wv[1]);
                    FMA4(&acc[j*4], hv.z, wv[2]);
                    FMA4(&acc[j*4], hv.w, wv[3]);
                }
            }
            size_t m0 = (size_t)cbase * KS;
#pragma unroll
            for (int j = 0; j < 8; j++) {
                int row = rg*8 + j;
                int cl = row >> 5;
                float4 zv;
                zv.x = acc[j*4+0] + bs[cl*64 + og*4+0];
                zv.y = acc[j*4+1] + bs[cl*64 + og*4+1];
                zv.z = acc[j*4+2] + bs[cl*64 + og*4+2];
                zv.w = acc[j*4+3] + bs[cl*64 + og*4+3];
                *(float4*)&g_h0[(m0 + row)*64 + og*4] = zv;
                tps[0]+=zv.x; tps[1]+=zv.y; tps[2]+=zv.z; tps[3]+=zv.w;
                tpq[0]+=zv.x*zv.x; tpq[1]+=zv.y*zv.y; tpq[2]+=zv.z*zv.z; tpq[3]+=zv.w*zv.w;
            }
        }
        __syncthreads();
#pragma unroll
        for (int i = 0; i < 4; i++) {
            atomicAdd(&ssum[og*4+i], tps[i]);
            atomicAdd(&ssq[og*4+i],  tpq[i]);
        }
        __syncthreads();
        if (t < 64) {
            atomicAdd(&g_sum[0][t], (double)ssum[t]);
            atomicAdd(&g_sq[0][t],  (double)ssq[t]);
        }
    }
}

/* ------------------------------ layer 1 ---------------------------------- */
__global__ void __launch_bounds__(128) k_layer1(const float* __restrict__ W1) {
    __shared__ float hs[128*64];
    __shared__ float ws[64*64];
    __shared__ float ssum[64], ssq[64];
    int t = threadIdx.x;
    if (t < 64) { ssum[t] = 0.f; ssq[t] = 0.f; }
    for (int i = t; i < 64*64; i += 128) {
        int cc = i >> 6, o = i & 63;
        ws[cc*64 + o] = W1[(size_t)o*64 + cc];
    }
    int rg = t >> 3, og = (t & 7) * 8;
    for (int tile = 0; tile < 2; tile++) {
        size_t m0 = (size_t)blockIdx.x * 256 + tile * 128;
        __syncthreads();
        for (int i = t; i < 128*16; i += 128) {
            int row = i >> 4, seg = i & 15;
            float4 v = *(const float4*)&g_h0[(m0 + row)*64 + seg*4];
            v.x = fmaxf(g_sc[0][seg*4+0]*v.x + g_sh[0][seg*4+0], 0.f);
            v.y = fmaxf(g_sc[0][seg*4+1]*v.y + g_sh[0][seg*4+1], 0.f);
            v.z = fmaxf(g_sc[0][seg*4+2]*v.z + g_sh[0][seg*4+2], 0.f);
            v.w = fmaxf(g_sc[0][seg*4+3]*v.w + g_sh[0][seg*4+3], 0.f);
            *(float4*)&hs[row*64 + seg*4] = v;
        }
        __syncthreads();
        float acc[64];
#pragma unroll
        for (int i = 0; i < 64; i++) acc[i] = 0.f;
#pragma unroll
        for (int cs = 0; cs < 64; cs += 4) {
            float4 wv[8];
#pragma unroll
            for (int c = 0; c < 4; c++) {
                wv[c*2]   = *(const float4*)&ws[(cs+c)*64 + og];
                wv[c*2+1] = *(const float4*)&ws[(cs+c)*64 + og + 4];
            }
#pragma unroll
            for (int j = 0; j < 8; j++) {
                float4 hv = *(const float4*)&hs[(rg*8+j)*64 + cs];
                float* a = &acc[j*8];
                FMA4(a,   hv.x, wv[0]); FMA4(a+4, hv.x, wv[1]);
                FMA4(a,   hv.y, wv[2]); FMA4(a+4, hv.y, wv[3]);
                FMA4(a,   hv.z, wv[4]); FMA4(a+4, hv.z, wv[5]);
                FMA4(a,   hv.w, wv[6]); FMA4(a+4, hv.w, wv[7]);
            }
        }
        float ps[8] = {0,0,0,0,0,0,0,0}, pq[8] = {0,0,0,0,0,0,0,0};
#pragma unroll
        for (int j = 0; j < 8; j++) {
            int row = rg*8 + j;
            float4 z0 = make_float4(acc[j*8+0], acc[j*8+1], acc[j*8+2], acc[j*8+3]);
            float4 z1 = make_float4(acc[j*8+4], acc[j*8+5], acc[j*8+6], acc[j*8+7]);
            *(float4*)&g_h1[(m0 + row)*64 + og]     = z0;
            *(float4*)&g_h1[(m0 + row)*64 + og + 4] = z1;
#pragma unroll
            for (int k = 0; k < 8; k++) {
                float z = acc[j*8+k];
                ps[k] += z; pq[k] += z*z;
            }
        }
#pragma unroll
        for (int k = 0; k < 8; k++) {
            atomicAdd(&ssum[og+k], ps[k]);
            atomicAdd(&ssq[og+k],  pq[k]);
        }
    }
    __syncthreads();
    if (t < 64) {
        atomicAdd(&g_sum[1][t], (double)ssum[t]);
        atomicAdd(&g_sq[1][t],  (double)ssq[t]);
    }
}

/* ------------------------------ layer 2 ---------------------------------- */
__global__ void __launch_bounds__(128) k_layer2(const float* __restrict__ W2) {
    extern __shared__ float dyn[];
    float* hs    = dyn;                  /* 64*64  = 4096  */
    float* ws    = dyn + 4096;           /* 64*128 = 8192  */
    float* redmx = dyn + 4096 + 8192;    /* 8*128  = 1024  */
    float* redmn = redmx + 1024;         /* 1024  */
    float* ssum  = redmn + 1024;         /* 128   */
    float* ssq   = ssum + 128;           /* 128   */
    int t = threadIdx.x;
    if (t < 128) { ssum[t] = 0.f; ssq[t] = 0.f; }
    for (int i = t; i < 64*128; i += 128) {
        int cc = i >> 7, o = i & 127;
        ws[cc*128 + o] = W2[(size_t)o*64 + cc];
    }
    int rg = t >> 4, og = (t & 15) * 8;
    for (int tile = 0; tile < 2; tile++) {
        int c0 = blockIdx.x * 4 + tile * 2;
        size_t m0 = (size_t)c0 * KS;
        __syncthreads();
        for (int i = t; i < 64*16; i += 128) {
            int row = i >> 4, seg = i & 15;
            float4 v = *(const float4*)&g_h1[(m0 + row)*64 + seg*4];
            v.x = fmaxf(g_sc[1][seg*4+0]*v.x + g_sh[1][seg*4+0], 0.f);
            v.y = fmaxf(g_sc[1][seg*4+1]*v.y + g_sh[1][seg*4+1], 0.f);
            v.z = fmaxf(g_sc[1][seg*4+2]*v.z + g_sh[1][seg*4+2], 0.f);
            v.w = fmaxf(g_sc[1][seg*4+3]*v.w + g_sh[1][seg*4+3], 0.f);
            *(float4*)&hs[row*64 + seg*4] = v;
        }
        __syncthreads();
        float acc[64];
#pragma unroll
        for (int i = 0; i < 64; i++) acc[i] = 0.f;
#pragma unroll
        for (int cs = 0; cs < 64; cs += 4) {
            float4 wv[8];
#pragma unroll
            for (int c = 0; c < 4; c++) {
                wv[c*2]   = *(const float4*)&ws[(cs+c)*128 + og];
                wv[c*2+1] = *(const float4*)&ws[(cs+c)*128 + og + 4];
            }
#pragma unroll
            for (int j = 0; j < 8; j++) {
                float4 hv = *(const float4*)&hs[(rg*8+j)*64 + cs];
                float* a = &acc[j*8];
                FMA4(a,   hv.x, wv[0]); FMA4(a+4, hv.x, wv[1]);
                FMA4(a,   hv.y, wv[2]); FMA4(a+4, hv.y, wv[3]);
                FMA4(a,   hv.z, wv[4]); FMA4(a+4, hv.z, wv[5]);
                FMA4(a,   hv.w, wv[6]); FMA4(a+4, hv.w, wv[7]);
            }
        }
#pragma unroll
        for (int k = 0; k < 8; k++) {
            int o = og + k;
            float mx = -1e30f, mn = 1e30f, ps = 0.f, pq = 0.f;
#pragma unroll
            for (int j = 0; j < 8; j++) {
                float z = acc[j*8+k];
                mx = fmaxf(mx, z); mn = fminf(mn, z);
                ps += z; pq += z*z;
            }
            redmx[rg*128 + o] = mx;
            redmn[rg*128 + o] = mn;
            atomicAdd(&ssum[o], ps);
            atomicAdd(&ssq[o],  pq);
        }
        __syncthreads();
#pragma unroll
        for (int p = t; p < 256; p += 128) {
            int cl = p >> 7, o = p & 127;
            float mx = -1e30f, mn = 1e30f;
#pragma unroll
            for (int r = 0; r < 4; r++) {
                mx = fmaxf(mx, redmx[(cl*4+r)*128 + o]);
                mn = fminf(mn, redmn[(cl*4+r)*128 + o]);
            }
            g_mx[(size_t)(c0+cl)*128 + o] = mx;
            g_mn[(size_t)(c0+cl)*128 + o] = mn;
        }
    }
    __syncthreads();
    if (t < 128) {
        atomicAdd(&g_sum[2][t], (double)ssum[t]);
        atomicAdd(&g_sq[2][t],  (double)ssq[t]);
    }
}

/* ----------------------------- BN fold ----------------------------------- */
__global__ void k_stats(int layer, const float* __restrict__ gm,
                        const float* __restrict__ bt, int nch) {
    int c = threadIdx.x;
    if (c < nch) {
        double mu = g_sum[layer][c] / (double)MTOT;
        double vr = g_sq[layer][c] / (double)MTOT - mu*mu;
        float sc = gm[c] * rsqrtf((float)vr + 1e-5f);
        g_sc[layer][c] = sc;
        g_sh[layer][c] = bt[c] - (float)mu * sc;
    }
}

/* ----------------------------- final pool -------------------------------- */
__global__ void k_final(float* __restrict__ out) {
    int i = blockIdx.x * blockDim.x + threadIdx.x;
    if (i >= Bn*Sn*128) return;
    int center = i >> 7, o = i & 127;
    int b = center / Sn, s = center % Sn;
    float sc = g_sc[2][o], sh = g_sh[2][o];
    float z = (sc >= 0.f) ? g_mx[(size_t)center*128 + o] : g_mn[(size_t)center*128 + o];
    out[ONP + ((size_t)b*128 + o)*Sn + s] = fmaxf(sc*z + sh, 0.f);
}

/* ------------------------------- launch ---------------------------------- */
extern "C" void kernel_launch(void* const* d_in, const int* in_sizes, int n_in,
                              void* d_out, int out_size) {
    const float* xyz = (const float*)d_in[0];
    const float* pts = (const float*)d_in[1];
    const float* W0  = (const float*)d_in[2];
    const float* g0  = (const float*)d_in[3];
    const float* b0  = (const float*)d_in[4];
    const float* W1  = (const float*)d_in[5];
    const float* g1  = (const float*)d_in[6];
    const float* b1  = (const float*)d_in[7];
    const float* W2  = (const float*)d_in[8];
    const float* g2  = (const float*)d_in[9];
    const float* b2  = (const float*)d_in[10];
    float* out = (float*)d_out;

    static bool attr_done = false;
    if (!attr_done) {
        cudaFuncSetAttribute(k_fused, cudaFuncAttributeMaxDynamicSharedMemorySize,
                             FS_TOTAL*sizeof(float));
        cudaFuncSetAttribute(k_layer2, cudaFuncAttributeMaxDynamicSharedMemorySize,
                             (4096+8192+1024+1024+256)*sizeof(float));
        attr_done = true;
    }

    k_pre<<<dim3(Nn/32, Dn/32, Bn), dim3(32, 8)>>>(pts);
    k_fused<<<Bn + NWORK, 1024, FS_TOTAL*sizeof(float)>>>(xyz, W0, out);
    k_stats<<<1, 128>>>(0, g0, b0, 64);
    k_layer1<<<MTOT/256, 128>>>(W1);
    k_stats<<<1, 128>>>(1, g1, b1, 64);
    k_layer2<<<Bn*Sn/4, 128, (4096+8192+1024+1024+256)*sizeof(float)>>>(W2);
    k_stats<<<1, 128>>>(2, g2, b2, 128);
    k_final<<<(Bn*Sn*128 + 255)/256, 256>>>(out);
}

// round 17
// speedup vs baseline: 1.0405x; 1.0115x over previous
#include <cuda_runtime.h>
#include <math.h>

#define Bn 8
#define Nn 8192
#define Sn 2048
#define Dn 64
#define KS 32
#define MTOT (Bn*Sn*KS)            /* 524288 rows through the MLP */
#define R2c 0.25f
#define NWORK 140                  /* worker blocks in fused kernel */
#define WTILE 16                   /* centers per worker tile */
#define NTILES (Bn*Sn/WTILE)       /* 1024 */

#define OXY2 (Bn*3*Sn)             /* 49152  */
#define ONP  (2*Bn*3*Sn)           /* 98304  */
#define OFPS (ONP + Bn*128*Sn)     /* 2195456 */

/* ------------------------- static device scratch ------------------------- */
__device__ float  g_pts_t[(size_t)Bn*Nn*Dn];   /* [B][N][64] */
__device__ int    g_fps[Bn*Sn];
__device__ float  g_h0[(size_t)MTOT*64];
__device__ float  g_h1[(size_t)MTOT*64];
__device__ float  g_mx[(size_t)Bn*Sn*128];
__device__ float  g_mn[(size_t)Bn*Sn*128];
__device__ double g_sum[3][128];
__device__ double g_sq[3][128];
__device__ float  g_sc[3][128];
__device__ float  g_sh[3][128];
__device__ volatile int g_prog[Bn];

/* ------------------------- packed f32x2 helpers -------------------------- */
typedef unsigned long long ull;
__device__ __forceinline__ ull pk2(float lo, float hi) {
    ull r; asm("mov.b64 %0,{%1,%2};" : "=l"(r) : "f"(lo), "f"(hi)); return r;
}
__device__ __forceinline__ void upk2(ull v, float& lo, float& hi) {
    asm("mov.b64 {%0,%1},%2;" : "=f"(lo), "=f"(hi) : "l"(v));
}
__device__ __forceinline__ ull add2(ull a, ull b) {
    ull r; asm("add.rn.f32x2 %0,%1,%2;" : "=l"(r) : "l"(a), "l"(b)); return r;
}
__device__ __forceinline__ ull mul2(ull a, ull b) {
    ull r; asm("mul.rn.f32x2 %0,%1,%2;" : "=l"(r) : "l"(a), "l"(b)); return r;
}
__device__ __forceinline__ ull fma2(ull a, ull b, ull c) {
    ull r; asm("fma.rn.f32x2 %0,%1,%2,%3;" : "=l"(r) : "l"(a), "l"(b), "l"(c)); return r;
}

/* --------------------- pre: transpose + zero + prog reset ---------------- */
__global__ void k_pre(const float* __restrict__ pts) {
    __shared__ float tile[32][33];
    int b = blockIdx.z, n0 = blockIdx.x * 32, c0 = blockIdx.y * 32;
    int tx = threadIdx.x, ty = threadIdx.y;
    if (blockIdx.x == 0 && blockIdx.y == 0 && blockIdx.z == 0) {
        int tid = ty*32 + tx;
        if (tid < 128) for (int l = 0; l < 3; l++) { g_sum[l][tid]=0.0; g_sq[l][tid]=0.0; }
        if (tid < Bn) g_prog[tid] = -1;
    }
    for (int i = ty; i < 32; i += 8)
        tile[i][tx] = pts[((size_t)b*Dn + c0 + i)*Nn + n0 + tx];
    __syncthreads();
    for (int i = ty; i < 32; i += 8)
        g_pts_t[((size_t)b*Nn + n0 + i)*Dn + c0 + tx] = tile[tx][i];
}

#define FMA4(A, H, WV) { (A)[0] += (H)*(WV).x; (A)[1] += (H)*(WV).y; \
                         (A)[2] += (H)*(WV).z; (A)[3] += (H)*(WV).w; }

/* floats of dynamic smem for the fused kernel (worker layout is the max) */
#define FS_HS   0                       /* 512*72 = 36864 */
#define FS_WSG  (512*72)                /* 72*64  = 4608  */
#define FS_WSB  (FS_WSG + 72*64)        /* 67*64  = 4288  */
#define FS_BS   (FS_WSB + 67*64)        /* 16*64  = 1024  */
#define FS_CF   (FS_BS + 1024)          /* 16*64  = 1024  */
#define FS_CXY  (FS_CF + 1024)          /* 48 */
#define FS_IDX  (FS_CXY + 48)           /* 512 ints */
#define FS_SSUM (FS_IDX + 512)          /* 64 */
#define FS_SSQ  (FS_SSUM + 64)          /* 64 */
#define FS_TOTAL (FS_SSQ + 64)          /* 48496 floats = 193984 B */

/* ------------------------------ FUSED ------------------------------------ */
__global__ void __launch_bounds__(1024) k_fused(const float* __restrict__ xyz,
                                                const float* __restrict__ W0,
                                                float* __restrict__ out) {
    extern __shared__ float sm[];
    __shared__ unsigned s_dv[2][32];
    __shared__ unsigned s_di[2][32];
    int t = threadIdx.x, warp = t >> 5, lane = t & 31;

    if (blockIdx.x < Bn) {
        /* --------------------------- FPS ---------------------------- */
        int b = blockIdx.x;
        float* sx = sm; float* sy = sm + Nn; float* sz = sm + 2*Nn;
        const float* xb = xyz + (size_t)b*3*Nn;
        for (int i = t; i < Nn; i += 1024) { sx[i]=xb[i]; sy[i]=xb[Nn+i]; sz[i]=xb[2*Nn+i]; }
        __syncthreads();
        ull px2[4], py2[4], pz2[4];
        float dist[8];
#pragma unroll
        for (int j = 0; j < 4; j++) {
            int i = t*8 + 2*j;
            px2[j] = pk2(sx[i], sx[i+1]);
            py2[j] = pk2(sy[i], sy[i+1]);
            pz2[j] = pk2(sz[i], sz[i+1]);
            dist[2*j] = 1e10f; dist[2*j+1] = 1e10f;
        }
        float fx = sx[0], fy = sy[0], fz = sz[0];
        if (t == 0) g_fps[b*Sn] = 0;
        for (int it = 1; it < Sn; it++) {
            ull nx = pk2(-fx, -fx), ny = pk2(-fy, -fy), nz = pk2(-fz, -fz);
            float bv = -1.0f; int bi = 0;
#pragma unroll
            for (int j = 0; j < 4; j++) {
                ull dx = add2(px2[j], nx);
                ull dy = add2(py2[j], ny);
                ull dz = add2(pz2[j], nz);
                ull s  = add2(add2(mul2(dx,dx), mul2(dy,dy)), mul2(dz,dz));
                float dlo, dhi; upk2(s, dlo, dhi);
                float n0 = fminf(dist[2*j],   dlo); dist[2*j]   = n0;
                if (n0 > bv) { bv = n0; bi = t*8 + 2*j; }
                float n1 = fminf(dist[2*j+1], dhi); dist[2*j+1] = n1;
                if (n1 > bv) { bv = n1; bi = t*8 + 2*j + 1; }
            }
            unsigned dvb  = __float_as_uint(bv);
            unsigned wmax = __reduce_max_sync(0xffffffffu, dvb);
            unsigned cand = (dvb == wmax) ? (unsigned)bi : 0xffffffffu;
            unsigned wbi  = __reduce_min_sync(0xffffffffu, cand);
            int p = it & 1;
            if (lane == 0) { s_dv[p][warp] = wmax; s_di[p][warp] = wbi; }
            __syncthreads();
            unsigned v    = s_dv[p][lane];
            unsigned gmax = __reduce_max_sync(0xffffffffu, v);
            unsigned c2   = (v == gmax) ? s_di[p][lane] : 0xffffffffu;
            unsigned gbi  = __reduce_min_sync(0xffffffffu, c2);
            fx = sx[gbi]; fy = sy[gbi]; fz = sz[gbi];
            if (t == 0) {
                g_fps[b*Sn + it] = (int)gbi;
                if ((it & 7) == 7) { __threadfence(); g_prog[b] = it; }
            }
        }
    } else {
        /* -------------------------- worker --------------------------- */
        int widx = blockIdx.x - Bn;
        float* hs  = sm + FS_HS;
        float* wsg = sm + FS_WSG;
        float* wsb = sm + FS_WSB;
        float* bs  = sm + FS_BS;
        float* cf  = sm + FS_CF;
        float* cxy = sm + FS_CXY;
        int*   idxs = (int*)(sm + FS_IDX);
        float* ssum = sm + FS_SSUM;
        float* ssq  = sm + FS_SSQ;
        for (int i = t; i < 72*64; i += 1024) {
            int cc = i >> 6, o = i & 63;
            float v = 0.f;
            if (cc < 64)      v = W0[(size_t)o*131 + 3 + cc];
            else if (cc < 67) v = W0[(size_t)o*131 + (cc - 64)];
            wsg[cc*64 + o] = v;
        }
        for (int i = t; i < 67*64; i += 1024) {
            int cc = i >> 6, o = i & 63;
            wsb[cc*64 + o] = (cc < 3) ? W0[(size_t)o*131 + cc]
                                      : W0[(size_t)o*131 + 67 + (cc - 3)];
        }
        if (t < 64) { ssum[t] = 0.f; ssq[t] = 0.f; }
        int rg = t >> 4, og = t & 15;
        float tps[4] = {0,0,0,0}, tpq[4] = {0,0,0,0};

        for (int tt = widx; tt < NTILES; tt += NWORK) {
            int b = tt >> 7, lt = tt & 127;
            const float* xb = xyz + (size_t)b*3*Nn;
            int cbase = b*Sn + lt*WTILE;
            int need = lt*WTILE + WTILE - 1;
            if (t == 0) {
                while (g_prog[b] < need) __nanosleep(1024);
            }
            __syncthreads();
            if (t < WTILE) {
                int s = lt*WTILE + t;
                int n = __ldcg(&g_fps[b*Sn + s]);
                float x = xb[n], y = xb[Nn+n], z = xb[2*Nn+n];
                out[((size_t)b*3+0)*Sn + s] = x;
                out[((size_t)b*3+1)*Sn + s] = y;
                out[((size_t)b*3+2)*Sn + s] = z;
                out[OXY2 + ((size_t)b*3+0)*Sn + s] = x;
                out[OXY2 + ((size_t)b*3+1)*Sn + s] = y;
                out[OXY2 + ((size_t)b*3+2)*Sn + s] = z;
                out[OFPS + b*Sn + s] = (float)n;
            }
            if (warp < 16) {
                int s = lt*WTILE + warp;
                int n = __ldcg(&g_fps[b*Sn + s]);
                float cx = xb[n], cy = xb[Nn+n], cz = xb[2*Nn+n];
                int found = 0, first = -1;
                for (int nb = 0; nb < Nn && found < KS; nb += 32) {
                    int i = nb + lane;
                    float dx = __fadd_rn(cx, -xb[i]);
                    float dy = __fadd_rn(cy, -xb[Nn+i]);
                    float dz = __fadd_rn(cz, -xb[2*Nn+i]);
                    float d2 = __fadd_rn(__fadd_rn(__fmul_rn(dx,dx), __fmul_rn(dy,dy)),
                                         __fmul_rn(dz,dz));
                    unsigned m = __ballot_sync(0xffffffffu, d2 <= R2c);
                    if (m) {
                        if (first < 0) first = nb + __ffs(m) - 1;
                        int pos = found + __popc(m & ((1u << lane) - 1u));
                        if (((m >> lane) & 1u) && pos < KS) idxs[warp*KS + pos] = i;
                        found += __popc(m);
                    }
                }
                if (found < KS && lane >= found && lane < KS) idxs[warp*KS + lane] = first;
            } else {
                int ti = t - 512;
                if (ti < 256) {
                    int row = ti >> 4, seg = ti & 15;
                    int n = __ldcg(&g_fps[b*Sn + lt*WTILE + row]);
                    *(float4*)&cf[row*64 + seg*4] =
                        *(const float4*)&g_pts_t[((size_t)b*Nn + n)*Dn + seg*4];
                } else if (ti < 304) {
                    int k = ti - 256;
                    int cl = k / 3, d = k % 3;
                    int n = __ldcg(&g_fps[b*Sn + lt*WTILE + cl]);
                    cxy[k] = xb[d*Nn + n];
                }
            }
            __syncthreads();
            for (int i = t; i < 512*16; i += 1024) {
                int row = i >> 4, seg = i & 15;
                int n = idxs[row];
                *(float4*)&hs[row*72 + seg*4] =
                    *(const float4*)&g_pts_t[((size_t)b*Nn + n)*Dn + seg*4];
            }
            for (int i = t; i < 512*8; i += 1024) {
                int row = i >> 3, cc = i & 7;
                float v = 0.f;
                if (cc < 3) v = xb[cc*Nn + idxs[row]];
                hs[row*72 + 64 + cc] = v;
            }
            if (t >= 512) {
                int ti = t - 512;
#pragma unroll
                for (int pp = 0; pp < 2; pp++) {
                    int p = ti + pp*512;
                    int cl = p >> 6, o = p & 63;
                    float acc = -(cxy[cl*3+0]*wsb[o] + cxy[cl*3+1]*wsb[64+o]
                                 + cxy[cl*3+2]*wsb[128+o]);
#pragma unroll 8
                    for (int k = 0; k < 64; k++) acc += cf[cl*64 + k]*wsb[(3+k)*64 + o];
                    bs[cl*64 + o] = acc;
                }
            }
            __syncthreads();
            float acc[32];
#pragma unroll
            for (int i = 0; i < 32; i++) acc[i] = 0.f;
#pragma unroll
            for (int cs = 0; cs < 72; cs += 4) {
                float4 wv[4];
#pragma unroll
                for (int i = 0; i < 4; i++) wv[i] = *(const float4*)&wsg[(cs+i)*64 + og*4];
#pragma unroll
                for (int j = 0; j < 8; j++) {
                    float4 hv = *(const float4*)&hs[(rg*8+j)*72 + cs];
                    FMA4(&acc[j*4], hv.x, wv[0]);
                    FMA4(&acc[j*4], hv.y, wv[1]);
                    FMA4(&acc[j*4], hv.z, wv[2]);
                    FMA4(&acc[j*4], hv.w, wv[3]);
                }
            }
            size_t m0 = (size_t)cbase * KS;
#pragma unroll
            for (int j = 0; j < 8; j++) {
                int row = rg*8 + j;
                int cl = row >> 5;
                float4 zv;
                zv.x = acc[j*4+0] + bs[cl*64 + og*4+0];
                zv.y = acc[j*4+1] + bs[cl*64 + og*4+1];
                zv.z = acc[j*4+2] + bs[cl*64 + og*4+2];
                zv.w = acc[j*4+3] + bs[cl*64 + og*4+3];
                *(float4*)&g_h0[(m0 + row)*64 + og*4] = zv;
                tps[0]+=zv.x; tps[1]+=zv.y; tps[2]+=zv.z; tps[3]+=zv.w;
                tpq[0]+=zv.x*zv.x; tpq[1]+=zv.y*zv.y; tpq[2]+=zv.z*zv.z; tpq[3]+=zv.w*zv.w;
            }
        }
        __syncthreads();
#pragma unroll
        for (int i = 0; i < 4; i++) {
            atomicAdd(&ssum[og*4+i], tps[i]);
            atomicAdd(&ssq[og*4+i],  tpq[i]);
        }
        __syncthreads();
        if (t < 64) {
            atomicAdd(&g_sum[0][t], (double)ssum[t]);
            atomicAdd(&g_sq[0][t],  (double)ssq[t]);
        }
    }
}

/* ------------------------------ layer 1 ---------------------------------- */
/* 8x8 register tile with packed fma.rn.f32x2 (FFMA2): 2 FMAs per issue */
__global__ void __launch_bounds__(128) k_layer1(const float* __restrict__ W1) {
    __shared__ float hs[128*64];
    __shared__ float ws[64*64];
    __shared__ float ssum[64], ssq[64];
    int t = threadIdx.x;
    if (t < 64) { ssum[t] = 0.f; ssq[t] = 0.f; }
    for (int i = t; i < 64*64; i += 128) {
        int cc = i >> 6, o = i & 63;
        ws[cc*64 + o] = W1[(size_t)o*64 + cc];
    }
    int rg = t >> 3, og = (t & 7) * 8;
    for (int tile = 0; tile < 2; tile++) {
        size_t m0 = (size_t)blockIdx.x * 256 + tile * 128;
        __syncthreads();
        for (int i = t; i < 128*16; i += 128) {
            int row = i >> 4, seg = i & 15;
            float4 v = *(const float4*)&g_h0[(m0 + row)*64 + seg*4];
            v.x = fmaxf(g_sc[0][seg*4+0]*v.x + g_sh[0][seg*4+0], 0.f);
            v.y = fmaxf(g_sc[0][seg*4+1]*v.y + g_sh[0][seg*4+1], 0.f);
            v.z = fmaxf(g_sc[0][seg*4+2]*v.z + g_sh[0][seg*4+2], 0.f);
            v.w = fmaxf(g_sc[0][seg*4+3]*v.w + g_sh[0][seg*4+3], 0.f);
            *(float4*)&hs[row*64 + seg*4] = v;
        }
        __syncthreads();
        ull acc[32];                      /* [row j][out-pair q] */
#pragma unroll
        for (int i = 0; i < 32; i++) acc[i] = 0ull;
#pragma unroll
        for (int cs = 0; cs < 64; cs += 4) {
            ulonglong2 wv[8];             /* [k c][half] : outs og..og+7 */
#pragma unroll
            for (int c = 0; c < 4; c++) {
                wv[c*2]   = *(const ulonglong2*)&ws[(cs+c)*64 + og];
                wv[c*2+1] = *(const ulonglong2*)&ws[(cs+c)*64 + og + 4];
            }
#pragma unroll
            for (int j = 0; j < 8; j++) {
                float4 hv = *(const float4*)&hs[(rg*8+j)*64 + cs];
                ull hx = pk2(hv.x, hv.x), hy = pk2(hv.y, hv.y);
                ull hz = pk2(hv.z, hv.z), hw = pk2(hv.w, hv.w);
                ull* a = &acc[j*4];
                a[0] = fma2(hx, wv[0].x, a[0]); a[1] = fma2(hx, wv[0].y, a[1]);
                a[2] = fma2(hx, wv[1].x, a[2]); a[3] = fma2(hx, wv[1].y, a[3]);
                a[0] = fma2(hy, wv[2].x, a[0]); a[1] = fma2(hy, wv[2].y, a[1]);
                a[2] = fma2(hy, wv[3].x, a[2]); a[3] = fma2(hy, wv[3].y, a[3]);
                a[0] = fma2(hz, wv[4].x, a[0]); a[1] = fma2(hz, wv[4].y, a[1]);
                a[2] = fma2(hz, wv[5].x, a[2]); a[3] = fma2(hz, wv[5].y, a[3]);
                a[0] = fma2(hw, wv[6].x, a[0]); a[1] = fma2(hw, wv[6].y, a[1]);
                a[2] = fma2(hw, wv[7].x, a[2]); a[3] = fma2(hw, wv[7].y, a[3]);
            }
        }
        float ps[8] = {0,0,0,0,0,0,0,0}, pq[8] = {0,0,0,0,0,0,0,0};
#pragma unroll
        for (int j = 0; j < 8; j++) {
            int row = rg*8 + j;
            ulonglong2 z0; z0.x = acc[j*4+0]; z0.y = acc[j*4+1];
            ulonglong2 z1; z1.x = acc[j*4+2]; z1.y = acc[j*4+3];
            *(ulonglong2*)&g_h1[(m0 + row)*64 + og]     = z0;
            *(ulonglong2*)&g_h1[(m0 + row)*64 + og + 4] = z1;
#pragma unroll
            for (int q = 0; q < 4; q++) {
                float lo, hi; upk2(acc[j*4+q], lo, hi);
                ps[q*2]   += lo; pq[q*2]   += lo*lo;
                ps[q*2+1] += hi; pq[q*2+1] += hi*hi;
            }
        }
#pragma unroll
        for (int k = 0; k < 8; k++) {
            atomicAdd(&ssum[og+k], ps[k]);
            atomicAdd(&ssq[og+k],  pq[k]);
        }
    }
    __syncthreads();
    if (t < 64) {
        atomicAdd(&g_sum[1][t], (double)ssum[t]);
        atomicAdd(&g_sq[1][t],  (double)ssq[t]);
    }
}

/* ------------------------------ layer 2 ---------------------------------- */
/* 8x8 register tile with FFMA2; h2 never materialized (max+min carried) */
__global__ void __launch_bounds__(128) k_layer2(const float* __restrict__ W2) {
    extern __shared__ float dyn[];
    float* hs    = dyn;                  /* 64*64  = 4096  */
    float* ws    = dyn + 4096;           /* 64*128 = 8192  */
    float* redmx = dyn + 4096 + 8192;    /* 8*128  = 1024  */
    float* redmn = redmx + 1024;         /* 1024  */
    float* ssum  = redmn + 1024;         /* 128   */
    float* ssq   = ssum + 128;           /* 128   */
    int t = threadIdx.x;
    if (t < 128) { ssum[t] = 0.f; ssq[t] = 0.f; }
    for (int i = t; i < 64*128; i += 128) {
        int cc = i >> 7, o = i & 127;
        ws[cc*128 + o] = W2[(size_t)o*64 + cc];
    }
    int rg = t >> 4, og = (t & 15) * 8;
    for (int tile = 0; tile < 2; tile++) {
        int c0 = blockIdx.x * 4 + tile * 2;
        size_t m0 = (size_t)c0 * KS;
        __syncthreads();
        for (int i = t; i < 64*16; i += 128) {
            int row = i >> 4, seg = i & 15;
            float4 v = *(const float4*)&g_h1[(m0 + row)*64 + seg*4];
            v.x = fmaxf(g_sc[1][seg*4+0]*v.x + g_sh[1][seg*4+0], 0.f);
            v.y = fmaxf(g_sc[1][seg*4+1]*v.y + g_sh[1][seg*4+1], 0.f);
            v.z = fmaxf(g_sc[1][seg*4+2]*v.z + g_sh[1][seg*4+2], 0.f);
            v.w = fmaxf(g_sc[1][seg*4+3]*v.w + g_sh[1][seg*4+3], 0.f);
            *(float4*)&hs[row*64 + seg*4] = v;
        }
        __syncthreads();
        ull acc[32];
#pragma unroll
        for (int i = 0; i < 32; i++) acc[i] = 0ull;
#pragma unroll
        for (int cs = 0; cs < 64; cs += 4) {
            ulonglong2 wv[8];
#pragma unroll
            for (int c = 0; c < 4; c++) {
                wv[c*2]   = *(const ulonglong2*)&ws[(cs+c)*128 + og];
                wv[c*2+1] = *(const ulonglong2*)&ws[(cs+c)*128 + og + 4];
            }
#pragma unroll
            for (int j = 0; j < 8; j++) {
                float4 hv = *(const float4*)&hs[(rg*8+j)*64 + cs];
                ull hx = pk2(hv.x, hv.x), hy = pk2(hv.y, hv.y);
                ull hz = pk2(hv.z, hv.z), hw = pk2(hv.w, hv.w);
                ull* a = &acc[j*4];
                a[0] = fma2(hx, wv[0].x, a[0]); a[1] = fma2(hx, wv[0].y, a[1]);
                a[2] = fma2(hx, wv[1].x, a[2]); a[3] = fma2(hx, wv[1].y, a[3]);
                a[0] = fma2(hy, wv[2].x, a[0]); a[1] = fma2(hy, wv[2].y, a[1]);
                a[2] = fma2(hy, wv[3].x, a[2]); a[3] = fma2(hy, wv[3].y, a[3]);
                a[0] = fma2(hz, wv[4].x, a[0]); a[1] = fma2(hz, wv[4].y, a[1]);
                a[2] = fma2(hz, wv[5].x, a[2]); a[3] = fma2(hz, wv[5].y, a[3]);
                a[0] = fma2(hw, wv[6].x, a[0]); a[1] = fma2(hw, wv[6].y, a[1]);
                a[2] = fma2(hw, wv[7].x, a[2]); a[3] = fma2(hw, wv[7].y, a[3]);
            }
        }
#pragma unroll
        for (int q = 0; q < 4; q++) {
            int o = og + q*2;
            float mxl = -1e30f, mnl = 1e30f, psl = 0.f, pql = 0.f;
            float mxh = -1e30f, mnh = 1e30f, psh = 0.f, pqh = 0.f;
#pragma unroll
            for (int j = 0; j < 8; j++) {
                float lo, hi; upk2(acc[j*4+q], lo, hi);
                mxl = fmaxf(mxl, lo); mnl = fminf(mnl, lo); psl += lo; pql += lo*lo;
                mxh = fmaxf(mxh, hi); mnh = fminf(mnh, hi); psh += hi; pqh += hi*hi;
            }
            redmx[rg*128 + o]   = mxl; redmn[rg*128 + o]   = mnl;
            redmx[rg*128 + o+1] = mxh; redmn[rg*128 + o+1] = mnh;
            atomicAdd(&ssum[o],   psl); atomicAdd(&ssq[o],   pql);
            atomicAdd(&ssum[o+1], psh); atomicAdd(&ssq[o+1], pqh);
        }
        __syncthreads();
#pragma unroll
        for (int p = t; p < 256; p += 128) {
            int cl = p >> 7, o = p & 127;
            float mx = -1e30f, mn = 1e30f;
#pragma unroll
            for (int r = 0; r < 4; r++) {
                mx = fmaxf(mx, redmx[(cl*4+r)*128 + o]);
                mn = fminf(mn, redmn[(cl*4+r)*128 + o]);
            }
            g_mx[(size_t)(c0+cl)*128 + o] = mx;
            g_mn[(size_t)(c0+cl)*128 + o] = mn;
        }
    }
    __syncthreads();
    if (t < 128) {
        atomicAdd(&g_sum[2][t], (double)ssum[t]);
        atomicAdd(&g_sq[2][t],  (double)ssq[t]);
    }
}

/* ----------------------------- BN fold ----------------------------------- */
__global__ void k_stats(int layer, const float* __restrict__ gm,
                        const float* __restrict__ bt, int nch) {
    int c = threadIdx.x;
    if (c < nch) {
        double mu = g_sum[layer][c] / (double)MTOT;
        double vr = g_sq[layer][c] / (double)MTOT - mu*mu;
        float sc = gm[c] * rsqrtf((float)vr + 1e-5f);
        g_sc[layer][c] = sc;
        g_sh[layer][c] = bt[c] - (float)mu * sc;
    }
}

/* ----------------------------- final pool -------------------------------- */
__global__ void k_final(float* __restrict__ out) {
    int i = blockIdx.x * blockDim.x + threadIdx.x;
    if (i >= Bn*Sn*128) return;
    int center = i >> 7, o = i & 127;
    int b = center / Sn, s = center % Sn;
    float sc = g_sc[2][o], sh = g_sh[2][o];
    float z = (sc >= 0.f) ? g_mx[(size_t)center*128 + o] : g_mn[(size_t)center*128 + o];
    out[ONP + ((size_t)b*128 + o)*Sn + s] = fmaxf(sc*z + sh, 0.f);
}

/* ------------------------------- launch ---------------------------------- */
extern "C" void kernel_launch(void* const* d_in, const int* in_sizes, int n_in,
                              void* d_out, int out_size) {
    const float* xyz = (const float*)d_in[0];
    const float* pts = (const float*)d_in[1];
    const float* W0  = (const float*)d_in[2];
    const float* g0  = (const float*)d_in[3];
    const float* b0  = (const float*)d_in[4];
    const float* W1  = (const float*)d_in[5];
    const float* g1  = (const float*)d_in[6];
    const float* b1  = (const float*)d_in[7];
    const float* W2  = (const float*)d_in[8];
    const float* g2  = (const float*)d_in[9];
    const float* b2  = (const float*)d_in[10];
    float* out = (float*)d_out;

    static bool attr_done = false;
    if (!attr_done) {
        cudaFuncSetAttribute(k_fused, cudaFuncAttributeMaxDynamicSharedMemorySize,
                             FS_TOTAL*sizeof(float));
        cudaFuncSetAttribute(k_layer2, cudaFuncAttributeMaxDynamicSharedMemorySize,
                             (4096+8192+1024+1024+256)*sizeof(float));
        attr_done = true;
    }

    k_pre<<<dim3(Nn/32, Dn/32, Bn), dim3(32, 8)>>>(pts);
    k_fused<<<Bn + NWORK, 1024, FS_TOTAL*sizeof(float)>>>(xyz, W0, out);
    k_stats<<<1, 128>>>(0, g0, b0, 64);
    k_layer1<<<MTOT/256, 128>>>(W1);
    k_stats<<<1, 128>>>(1, g1, b1, 64);
    k_layer2<<<Bn*Sn/4, 128, (4096+8192+1024+1024+256)*sizeof(float)>>>(W2);
    k_stats<<<1, 128>>>(2, g2, b2, 128);
    k_final<<<(Bn*Sn*128 + 255)/256, 256>>>(out);
}